// round 16
// baseline (speedup 1.0000x reference)
#include <cuda_runtime.h>
#include <cuda_bf16.h>
#include <math.h>

#define NTOK 64
#define DIM 128
#define NHEADS 4
#define SCALE 0.1767766952966369f   // 32^-0.5

#define XQS 132          // row-major x/q/O stride
#define KTS 136          // kTp row stride (B-paired)
#define VSS 264          // vsp row stride (B-paired)
#define WQ4S 768         // packed Wqkv row stride
#define WP4S 256         // packed Wproj row stride

#define OFF_KT 8448
#define OFF_VS 17152
#define SMEM_FLOATS 25600            // 102,400 B -> 2 CTAs / SM

__device__ float g_table[225 * 4];
__device__ uint2 g_biasf[4 * 4 * 8 * 32];   // bf16x4 C-fragment-packed bias
__device__ float g_wqkv_p4[64 * WQ4S];      // q-columns pre-scaled by SCALE
__device__ float g_wproj_p4[64 * WP4S];

__device__ __forceinline__ unsigned f2tf(float x) {
    unsigned r; asm("cvt.rna.tf32.f32 %0, %1;" : "=r"(r) : "f"(x)); return r;
}
__device__ __forceinline__ float uaf(unsigned x) { return __uint_as_float(x); }
__device__ __forceinline__ unsigned fau(float x) { return __float_as_uint(x); }

__device__ __forceinline__ void mma8(float* c, const unsigned* a, const unsigned* b) {
    asm volatile(
        "mma.sync.aligned.m16n8k8.row.col.f32.tf32.tf32.f32 "
        "{%0,%1,%2,%3}, {%4,%5,%6,%7}, {%8,%9}, {%0,%1,%2,%3};"
        : "+f"(c[0]), "+f"(c[1]), "+f"(c[2]), "+f"(c[3])
        : "r"(a[0]), "r"(a[1]), "r"(a[2]), "r"(a[3]), "r"(b[0]), "r"(b[1]));
}

__device__ __forceinline__ int bpack_idx(int k, int n, int stride) {
    int rb = ((k >> 3) << 2) + (k & 3);
    return rb * stride + ((n >> 4) << 5) + ((n & 7) << 2)
         + (((n >> 3) & 1) << 1) + ((k >> 2) & 1);
}

// C-layout fragment -> A-fragment for same 8-col group as k-dim (quad shuffles)
__device__ __forceinline__ void c2a(const float* c4, int s0, int s1, int odd,
                                    unsigned* af) {
    float x0 = __shfl_sync(0xffffffffu, c4[0], s0);
    float x1 = __shfl_sync(0xffffffffu, c4[1], s0);
    float y0 = __shfl_sync(0xffffffffu, c4[2], s0);
    float y1 = __shfl_sync(0xffffffffu, c4[3], s0);
    float z0 = __shfl_sync(0xffffffffu, c4[0], s1);
    float z1 = __shfl_sync(0xffffffffu, c4[1], s1);
    float w0 = __shfl_sync(0xffffffffu, c4[2], s1);
    float w1 = __shfl_sync(0xffffffffu, c4[3], s1);
    af[0] = fau(odd ? x1 : x0);
    af[1] = fau(odd ? y1 : y0);
    af[2] = fau(odd ? z1 : z0);
    af[3] = fau(odd ? w1 : w0);
}

// ---------------------------------------------------------------------------
// Setup A1: CPB table
// ---------------------------------------------------------------------------
__global__ void cpb_table_kernel(const float* __restrict__ cpb_w1,
                                 const float* __restrict__ cpb_b1,
                                 const float* __restrict__ cpb_w2,
                                 const float* __restrict__ h_times,
                                 const float* __restrict__ pow_para,
                                 const float* __restrict__ ws1,
                                 const float* __restrict__ ws2,
                                 const float* __restrict__ coords)
{
    __shared__ float red[128][4];
    const int t = blockIdx.x;
    const int tid = threadIdx.x;

    float ht = log1pf(expf(h_times[0]));
    float pp = 1.0f / (1.0f + expf(-pow_para[0]));
    float ws = log1pf(expf(ws1[0])) / log1pf(expf(ws2[0]));
    float t0 = coords[t * 2 + 0] * ht;
    float t1 = coords[t * 2 + 1] * ht;
    float s0 = (float)((t0 > 0.f) - (t0 < 0.f));
    float s1 = (float)((t1 > 0.f) - (t1 < 0.f));
    t0 = s0 * powf(fabsf(t0) + 1e-6f, pp) * ws;
    t1 = s1 * powf(fabsf(t1) + 1e-6f, pp) * ws;

    float a0 = 0.f, a1 = 0.f, a2 = 0.f, a3 = 0.f;
    for (int j = tid; j < 512; j += 128) {
        float hsum = fmaf(t0, cpb_w1[j], fmaf(t1, cpb_w1[512 + j], cpb_b1[j]));
        hsum = fmaxf(hsum, 0.f);
        a0 = fmaf(hsum, cpb_w2[j * 4 + 0], a0);
        a1 = fmaf(hsum, cpb_w2[j * 4 + 1], a1);
        a2 = fmaf(hsum, cpb_w2[j * 4 + 2], a2);
        a3 = fmaf(hsum, cpb_w2[j * 4 + 3], a3);
    }
    red[tid][0] = a0; red[tid][1] = a1; red[tid][2] = a2; red[tid][3] = a3;
    __syncthreads();
    for (int s = 64; s > 0; s >>= 1) {
        if (tid < s) {
            red[tid][0] += red[tid + s][0];
            red[tid][1] += red[tid + s][1];
            red[tid][2] += red[tid + s][2];
            red[tid][3] += red[tid + s][3];
        }
        __syncthreads();
    }
    if (tid < 4) g_table[t * 4 + tid] = red[0][tid];
}

// ---------------------------------------------------------------------------
// Setup A2: bias -> bf16 C-fragment-packed layout
// ---------------------------------------------------------------------------
__global__ void bias_expand_kernel(const int* __restrict__ rel_index)
{
    int i = blockIdx.x * blockDim.x + threadIdx.x;
    if (i >= 4 * 4 * 8 * 32) return;
    int lane = i & 31, nt = (i >> 5) & 7, mtg = (i >> 8) & 3, h = i >> 10;
    int lr = lane >> 2, lc = lane & 3;
    int r0 = mtg * 16 + lr, r1 = r0 + 8;
    int c = nt * 8 + 2 * lc;
    float b00 = g_table[rel_index[r0 * 64 + c] * 4 + h];
    float b01 = g_table[rel_index[r0 * 64 + c + 1] * 4 + h];
    float b10 = g_table[rel_index[r1 * 64 + c] * 4 + h];
    float b11 = g_table[rel_index[r1 * 64 + c + 1] * 4 + h];
    __nv_bfloat162 lo = __floats2bfloat162_rn(b00, b01);
    __nv_bfloat162 hi = __floats2bfloat162_rn(b10, b11);
    uint2 v;
    v.x = *reinterpret_cast<unsigned*>(&lo);
    v.y = *reinterpret_cast<unsigned*>(&hi);
    g_biasf[i] = v;
}

// ---------------------------------------------------------------------------
// Setup B: tf32-round + B-pair-pack weights; q-columns pre-scaled by SCALE
// ---------------------------------------------------------------------------
__global__ void pack_kernel(const float* __restrict__ Wqkv,
                            const float* __restrict__ Wproj)
{
    int tid = blockIdx.x * blockDim.x + threadIdx.x;
    int stride = gridDim.x * blockDim.x;
    for (int i = tid; i < 128 * 384; i += stride) {
        int k = i / 384, n = i % 384;
        float w = Wqkv[(size_t)k * 384 + n];
        if (n < 128) w *= SCALE;          // fold q scale into weights
        g_wqkv_p4[bpack_idx(k, n, WQ4S)] = uaf(f2tf(w));
    }
    for (int i = tid; i < 128 * 128; i += stride) {
        int k = i / 128, n = i % 128;
        g_wproj_p4[bpack_idx(k, n, WP4S)] = uaf(f2tf(Wproj[(size_t)k * 128 + n]));
    }
}

// ---------------------------------------------------------------------------
// Main fused kernel: 1 window / CTA, 256 threads = 8 warps, 2 CTAs / SM
// ---------------------------------------------------------------------------
__global__ void __launch_bounds__(256, 2)
attn_kernel(const float* __restrict__ x,
            const float* __restrict__ bproj,
            float*       __restrict__ out)
{
    extern __shared__ float sm[];
    float* xq  = sm;              // row-major tf32: x, later O
    float* kTp = sm + OFF_KT;     // tf32 k, B-paired [channel][token]
    float* vsp = sm + OFF_VS;     // tf32 v, B-paired [token][channel]

    const int tid  = threadIdx.x;
    const int lane = tid & 31;
    const int wid  = tid >> 5;    // 0..7
    const int lr   = lane >> 2;
    const int lc   = lane & 3;
    const int b    = blockIdx.x;
    const int h    = wid >> 1;
    const int mh   = wid & 1;

    // ---- load x -> tf32, row-major ----
    const float4* xb = (const float4*)(x + (size_t)b * NTOK * DIM);
    #pragma unroll
    for (int i = 0; i < 8; i++) {
        int f = tid + i * 256;
        float4 v = xb[f];
        int r = f >> 5, c0 = (f & 31) << 2;
        float4 w = make_float4(uaf(f2tf(v.x)), uaf(f2tf(v.y)),
                               uaf(f2tf(v.z)), uaf(f2tf(v.w)));
        *(float4*)(xq + r * XQS + c0) = w;
    }
    __syncthreads();

    // ============ Phase 1 (merged): kv slab + q tile, shared A-fragments =====
    // Weight loads software-pipelined one kg ahead.
    float qacc[2][4][4];
    {
        const float* wkv_base = g_wqkv_p4 + ((8 + wid * 2) * 8 + lr) * 4;
        const float* wq_base  = g_wqkv_p4 + ((h * 2) * 8 + lr) * 4;
        float kacc[4][4][4];
        #pragma unroll
        for (int mt = 0; mt < 4; mt++)
            #pragma unroll
            for (int nt = 0; nt < 4; nt++)
                #pragma unroll
                for (int e = 0; e < 4; e++) kacc[mt][nt][e] = 0.f;
        #pragma unroll
        for (int mt = 0; mt < 2; mt++)
            #pragma unroll
            for (int nt = 0; nt < 4; nt++)
                #pragma unroll
                for (int e = 0; e < 4; e++) qacc[mt][nt][e] = 0.f;

        // preload kg = 0
        float4 bk0 = *(const float4*)(wkv_base + lc * WQ4S);
        float4 bk1 = *(const float4*)(wkv_base + lc * WQ4S + 32);
        float4 bq0 = *(const float4*)(wq_base  + lc * WQ4S);
        float4 bq1 = *(const float4*)(wq_base  + lc * WQ4S + 32);

        #pragma unroll
        for (int kg = 0; kg < 16; kg++) {
            // consume into operand arrays (register aliases)
            unsigned kb[4][2] = { { fau(bk0.x), fau(bk0.y) }, { fau(bk0.z), fau(bk0.w) },
                                  { fau(bk1.x), fau(bk1.y) }, { fau(bk1.z), fau(bk1.w) } };
            unsigned qb[4][2] = { { fau(bq0.x), fau(bq0.y) }, { fau(bq0.z), fau(bq0.w) },
                                  { fau(bq1.x), fau(bq1.y) }, { fau(bq1.z), fau(bq1.w) } };
            // issue next iteration's weight loads (latency hides under 24 MMAs)
            if (kg < 15) {
                const float* wrk = wkv_base + ((kg + 1) * 4 + lc) * WQ4S;
                const float* wrq = wq_base  + ((kg + 1) * 4 + lc) * WQ4S;
                bk0 = *(const float4*)(wrk);
                bk1 = *(const float4*)(wrk + 32);
                bq0 = *(const float4*)(wrq);
                bq1 = *(const float4*)(wrq + 32);
            }
            #pragma unroll
            for (int mt = 0; mt < 4; mt++) {
                const float* ap = xq + (mt * 16 + lr) * XQS + kg * 8 + lc;
                unsigned af[4] = { fau(ap[0]), fau(ap[8 * XQS]),
                                   fau(ap[4]), fau(ap[8 * XQS + 4]) };
                mma8(kacc[mt][0], af, kb[0]);
                mma8(kacc[mt][1], af, kb[1]);
                mma8(kacc[mt][2], af, kb[2]);
                mma8(kacc[mt][3], af, kb[3]);
                if ((mt >> 1) == mh) {           // warp-uniform branch
                    int qi = mt & 1;
                    mma8(qacc[qi][0], af, qb[0]);
                    mma8(qacc[qi][1], af, qb[1]);
                    mma8(qacc[qi][2], af, qb[2]);
                    mma8(qacc[qi][3], af, qb[3]);
                }
            }
        }

        // scatter k / v (tf32-rounded)
        if (wid < 4) {
            #pragma unroll
            for (int mt = 0; mt < 4; mt++)
                #pragma unroll
                for (int nt = 0; nt < 4; nt++)
                    #pragma unroll
                    for (int eh = 0; eh < 2; eh++)
                        #pragma unroll
                        for (int e = 0; e < 2; e++) {
                            int row = mt * 16 + lr + 8 * eh;
                            int ch = wid * 32 + nt * 8 + 2 * lc + e;
                            kTp[bpack_idx(ch, row, KTS)] =
                                uaf(f2tf(kacc[mt][nt][2 * eh + e]));
                        }
        } else {
            #pragma unroll
            for (int mt = 0; mt < 4; mt++)
                #pragma unroll
                for (int nt = 0; nt < 4; nt++)
                    #pragma unroll
                    for (int eh = 0; eh < 2; eh++)
                        #pragma unroll
                        for (int e = 0; e < 2; e++) {
                            int row = mt * 16 + lr + 8 * eh;
                            int ch = (wid - 4) * 32 + nt * 8 + 2 * lc + e;
                            vsp[bpack_idx(row, ch, VSS)] =
                                uaf(f2tf(kacc[mt][nt][2 * eh + e]));
                        }
        }

        // round q in registers (scale already folded into weights)
        #pragma unroll
        for (int mt = 0; mt < 2; mt++)
            #pragma unroll
            for (int nt = 0; nt < 4; nt++)
                #pragma unroll
                for (int e = 0; e < 4; e++)
                    qacc[mt][nt][e] = uaf(f2tf(qacc[mt][nt][e]));
    }
    __syncthreads();

    // ============ Phases 2-4 fused, BOTH 16-row stripes interleaved ==========
    const int s0 = lr * 4 + (lc >> 1), s1 = s0 + 2;
    const int odd = lc & 1;

    // q C-layout -> A-fragments for both stripes
    unsigned aq[2][4][4];
    #pragma unroll
    for (int mt = 0; mt < 2; mt++)
        #pragma unroll
        for (int kg = 0; kg < 4; kg++) c2a(qacc[mt][kg], s0, s1, odd, aq[mt][kg]);

    // S = Q K^T for both stripes; B fragments shared
    float sacc[2][8][4];
    #pragma unroll
    for (int mt = 0; mt < 2; mt++)
        #pragma unroll
        for (int nt = 0; nt < 8; nt++)
            #pragma unroll
            for (int e = 0; e < 4; e++) sacc[mt][nt][e] = 0.f;

    #pragma unroll
    for (int kg = 0; kg < 4; kg++) {
        const float* krow = kTp + ((h * 4 + kg) * 4 + lc) * KTS;
        #pragma unroll
        for (int np = 0; np < 4; np++) {
            float4 kv4 = *(const float4*)(krow + np * 32 + lr * 4);
            unsigned b0[2] = { fau(kv4.x), fau(kv4.y) };
            unsigned b1[2] = { fau(kv4.z), fau(kv4.w) };
            mma8(sacc[0][2 * np],     aq[0][kg], b0);
            mma8(sacc[0][2 * np + 1], aq[0][kg], b1);
            mma8(sacc[1][2 * np],     aq[1][kg], b0);
            mma8(sacc[1][2 * np + 1], aq[1][kg], b1);
        }
    }

    // bias for both stripes (batched loads)
    uint2 bfr[2][8];
    #pragma unroll
    for (int mt = 0; mt < 2; mt++) {
        const uint2* bp = g_biasf + ((h * 4 + (2 * mh + mt)) * 8) * 32 + lane;
        #pragma unroll
        for (int nt = 0; nt < 8; nt++) bfr[mt][nt] = bp[nt * 32];
    }

    // softmax WITHOUT max-subtraction (scores are tiny; exact math)
    float i0[2], i1[2];
    #pragma unroll
    for (int mt = 0; mt < 2; mt++) {
        float sum0 = 0.f, sum1 = 0.f;
        #pragma unroll
        for (int nt = 0; nt < 8; nt++) {
            __nv_bfloat162 lo = *reinterpret_cast<__nv_bfloat162*>(&bfr[mt][nt].x);
            __nv_bfloat162 hi = *reinterpret_cast<__nv_bfloat162*>(&bfr[mt][nt].y);
            float2 flo = __bfloat1622float2(lo);
            float2 fhi = __bfloat1622float2(hi);
            sacc[mt][nt][0] = __expf(sacc[mt][nt][0] + flo.x); sum0 += sacc[mt][nt][0];
            sacc[mt][nt][1] = __expf(sacc[mt][nt][1] + flo.y); sum0 += sacc[mt][nt][1];
            sacc[mt][nt][2] = __expf(sacc[mt][nt][2] + fhi.x); sum1 += sacc[mt][nt][2];
            sacc[mt][nt][3] = __expf(sacc[mt][nt][3] + fhi.y); sum1 += sacc[mt][nt][3];
        }
        sum0 += __shfl_xor_sync(0xffffffffu, sum0, 1);
        sum0 += __shfl_xor_sync(0xffffffffu, sum0, 2);
        sum1 += __shfl_xor_sync(0xffffffffu, sum1, 1);
        sum1 += __shfl_xor_sync(0xffffffffu, sum1, 2);
        i0[mt] = 1.0f / sum0;
        i1[mt] = 1.0f / sum1;
    }
    #pragma unroll
    for (int mt = 0; mt < 2; mt++)
        #pragma unroll
        for (int nt = 0; nt < 8; nt++) {
            sacc[mt][nt][0] = uaf(f2tf(sacc[mt][nt][0] * i0[mt]));
            sacc[mt][nt][1] = uaf(f2tf(sacc[mt][nt][1] * i0[mt]));
            sacc[mt][nt][2] = uaf(f2tf(sacc[mt][nt][2] * i1[mt]));
            sacc[mt][nt][3] = uaf(f2tf(sacc[mt][nt][3] * i1[mt]));
        }

    // O = P V for both stripes; V fragments shared
    float oacc[2][4][4];
    #pragma unroll
    for (int mt = 0; mt < 2; mt++)
        #pragma unroll
        for (int nt2 = 0; nt2 < 4; nt2++)
            #pragma unroll
            for (int e = 0; e < 4; e++) oacc[mt][nt2][e] = 0.f;

    #pragma unroll
    for (int kg = 0; kg < 8; kg++) {
        unsigned ap0[4], ap1[4];
        c2a(sacc[0][kg], s0, s1, odd, ap0);
        c2a(sacc[1][kg], s0, s1, odd, ap1);
        const float* vrow = vsp + (kg * 4 + lc) * VSS;
        #pragma unroll
        for (int np2 = 0; np2 < 2; np2++) {
            float4 vv = *(const float4*)(vrow + (2 * h + np2) * 32 + lr * 4);
            unsigned b0[2] = { fau(vv.x), fau(vv.y) };
            unsigned b1[2] = { fau(vv.z), fau(vv.w) };
            mma8(oacc[0][np2 * 2],     ap0, b0);
            mma8(oacc[0][np2 * 2 + 1], ap0, b1);
            mma8(oacc[1][np2 * 2],     ap1, b0);
            mma8(oacc[1][np2 * 2 + 1], ap1, b1);
        }
    }

    // O -> xq row-major (x dead)
    #pragma unroll
    for (int mt = 0; mt < 2; mt++)
        #pragma unroll
        for (int nt2 = 0; nt2 < 4; nt2++)
            #pragma unroll
            for (int eh = 0; eh < 2; eh++)
                #pragma unroll
                for (int e = 0; e < 2; e++) {
                    int row = mh * 32 + mt * 16 + lr + 8 * eh;
                    int ch = h * 32 + nt2 * 8 + 2 * lc + e;
                    xq[row * XQS + ch] = uaf(f2tf(oacc[mt][nt2][2 * eh + e]));
                }

    // phase-5 first weight fragments: issue loads BEFORE the barrier
    const int mh5 = wid & 1;
    const int sl  = wid >> 1;
    const float* wbase = g_wproj_p4 + ((sl * 2) * 8 + lr) * 4;
    float4 bv0 = *(const float4*)(wbase + lc * WP4S);
    float4 bv1 = *(const float4*)(wbase + lc * WP4S + 32);
    float4 bv0b = *(const float4*)(wbase + (4 + lc) * WP4S);
    float4 bv1b = *(const float4*)(wbase + (4 + lc) * WP4S + 32);
    __syncthreads();

    // =================== Phase 5: Y = tf32(O) @ tf32(Wproj) + b ===============
    // prefetch depth 2
    {
        float acc5[2][4][4];
        #pragma unroll
        for (int m = 0; m < 2; m++)
            #pragma unroll
            for (int j = 0; j < 4; j++)
                #pragma unroll
                for (int e = 0; e < 4; e++) acc5[m][j][e] = 0.f;

        #pragma unroll
        for (int kg = 0; kg < 16; kg++) {
            unsigned b0[2] = { fau(bv0.x), fau(bv0.y) };
            unsigned b1[2] = { fau(bv0.z), fau(bv0.w) };
            unsigned b2[2] = { fau(bv1.x), fau(bv1.y) };
            unsigned b3[2] = { fau(bv1.z), fau(bv1.w) };
            bv0 = bv0b; bv1 = bv1b;
            if (kg < 14) {
                bv0b = *(const float4*)(wbase + ((kg + 2) * 4 + lc) * WP4S);
                bv1b = *(const float4*)(wbase + ((kg + 2) * 4 + lc) * WP4S + 32);
            }
            #pragma unroll
            for (int m = 0; m < 2; m++) {
                const float* ap = xq + ((mh5 * 2 + m) * 16 + lr) * XQS + kg * 8 + lc;
                unsigned af[4] = { fau(ap[0]), fau(ap[8 * XQS]),
                                   fau(ap[4]), fau(ap[8 * XQS + 4]) };
                mma8(acc5[m][0], af, b0);
                mma8(acc5[m][1], af, b1);
                mma8(acc5[m][2], af, b2);
                mma8(acc5[m][3], af, b3);
            }
        }

        float* obp = out + (size_t)b * NTOK * DIM;
        #pragma unroll
        for (int m = 0; m < 2; m++)
            #pragma unroll
            for (int j = 0; j < 4; j++) {
                int c0 = sl * 32 + j * 8 + 2 * lc;
                float2 bb = *(const float2*)(bproj + c0);
                #pragma unroll
                for (int eh = 0; eh < 2; eh++) {
                    int row = (mh5 * 2 + m) * 16 + lr + 8 * eh;
                    *(float2*)(obp + row * DIM + c0) =
                        make_float2(acc5[m][j][2 * eh] + bb.x,
                                    acc5[m][j][2 * eh + 1] + bb.y);
                }
            }
    }
}

// ---------------------------------------------------------------------------
// Launch
// ---------------------------------------------------------------------------
extern "C" void kernel_launch(void* const* d_in, const int* in_sizes, int n_in,
                              void* d_out, int out_size)
{
    const float* x        = (const float*)d_in[0];
    const float* Wqkv     = (const float*)d_in[1];
    const float* Wproj    = (const float*)d_in[2];
    const float* bproj    = (const float*)d_in[3];
    const float* cpb_w1   = (const float*)d_in[4];
    const float* cpb_b1   = (const float*)d_in[5];
    const float* cpb_w2   = (const float*)d_in[6];
    const float* h_times  = (const float*)d_in[7];
    const float* pow_para = (const float*)d_in[8];
    const float* ws1      = (const float*)d_in[9];
    const float* ws2      = (const float*)d_in[10];
    const int*   rel_idx  = (const int*)d_in[11];
    const float* coords   = (const float*)d_in[12];

    int nwin = in_sizes[0] / (NTOK * DIM);

    int smem_bytes = SMEM_FLOATS * (int)sizeof(float);
    cudaFuncSetAttribute(attn_kernel,
                         cudaFuncAttributeMaxDynamicSharedMemorySize, smem_bytes);

    cpb_table_kernel<<<225, 128>>>(cpb_w1, cpb_b1, cpb_w2, h_times, pow_para,
                                   ws1, ws2, coords);
    bias_expand_kernel<<<16, 256>>>(rel_idx);
    pack_kernel<<<192, 256>>>(Wqkv, Wproj);
    attn_kernel<<<nwin, 256, smem_bytes>>>(x, bproj, (float*)d_out);
}

// round 17
// speedup vs baseline: 1.2841x; 1.2841x over previous
#include <cuda_runtime.h>
#include <cuda_bf16.h>
#include <math.h>

#define NTOK 64
#define DIM 128
#define NHEADS 4
#define SCALE 0.1767766952966369f   // 32^-0.5

#define XQS 132          // row-major x/q/O stride
#define KTS 136          // kTp row stride (B-paired)
#define VSS 264          // vsp row stride (B-paired)
#define WQ4S 768         // packed Wqkv row stride
#define WP4S 256         // packed Wproj row stride

#define OFF_KT 8448
#define OFF_VS 17152
#define SMEM_FLOATS 25600            // 102,400 B -> 2 CTAs / SM

__device__ float g_table[225 * 4];
__device__ uint2 g_biasf[4 * 4 * 8 * 32];   // bf16x4 C-fragment-packed bias
__device__ float g_wqkv_p4[64 * WQ4S];      // q-columns pre-scaled by SCALE
__device__ float g_wproj_p4[64 * WP4S];

__device__ __forceinline__ unsigned f2tf(float x) {
    unsigned r; asm("cvt.rna.tf32.f32 %0, %1;" : "=r"(r) : "f"(x)); return r;
}
__device__ __forceinline__ float uaf(unsigned x) { return __uint_as_float(x); }
__device__ __forceinline__ unsigned fau(float x) { return __float_as_uint(x); }

__device__ __forceinline__ void mma8(float* c, const unsigned* a, const unsigned* b) {
    asm volatile(
        "mma.sync.aligned.m16n8k8.row.col.f32.tf32.tf32.f32 "
        "{%0,%1,%2,%3}, {%4,%5,%6,%7}, {%8,%9}, {%0,%1,%2,%3};"
        : "+f"(c[0]), "+f"(c[1]), "+f"(c[2]), "+f"(c[3])
        : "r"(a[0]), "r"(a[1]), "r"(a[2]), "r"(a[3]), "r"(b[0]), "r"(b[1]));
}

__device__ __forceinline__ int bpack_idx(int k, int n, int stride) {
    int rb = ((k >> 3) << 2) + (k & 3);
    return rb * stride + ((n >> 4) << 5) + ((n & 7) << 2)
         + (((n >> 3) & 1) << 1) + ((k >> 2) & 1);
}

// C-layout fragment -> A-fragment for same 8-col group as k-dim (quad shuffles)
__device__ __forceinline__ void c2a(const float* c4, int s0, int s1, int odd,
                                    unsigned* af) {
    float x0 = __shfl_sync(0xffffffffu, c4[0], s0);
    float x1 = __shfl_sync(0xffffffffu, c4[1], s0);
    float y0 = __shfl_sync(0xffffffffu, c4[2], s0);
    float y1 = __shfl_sync(0xffffffffu, c4[3], s0);
    float z0 = __shfl_sync(0xffffffffu, c4[0], s1);
    float z1 = __shfl_sync(0xffffffffu, c4[1], s1);
    float w0 = __shfl_sync(0xffffffffu, c4[2], s1);
    float w1 = __shfl_sync(0xffffffffu, c4[3], s1);
    af[0] = fau(odd ? x1 : x0);
    af[1] = fau(odd ? y1 : y0);
    af[2] = fau(odd ? z1 : z0);
    af[3] = fau(odd ? w1 : w0);
}

// ---------------------------------------------------------------------------
// Setup A1: CPB table
// ---------------------------------------------------------------------------
__global__ void cpb_table_kernel(const float* __restrict__ cpb_w1,
                                 const float* __restrict__ cpb_b1,
                                 const float* __restrict__ cpb_w2,
                                 const float* __restrict__ h_times,
                                 const float* __restrict__ pow_para,
                                 const float* __restrict__ ws1,
                                 const float* __restrict__ ws2,
                                 const float* __restrict__ coords)
{
    __shared__ float red[128][4];
    const int t = blockIdx.x;
    const int tid = threadIdx.x;

    float ht = log1pf(expf(h_times[0]));
    float pp = 1.0f / (1.0f + expf(-pow_para[0]));
    float ws = log1pf(expf(ws1[0])) / log1pf(expf(ws2[0]));
    float t0 = coords[t * 2 + 0] * ht;
    float t1 = coords[t * 2 + 1] * ht;
    float s0 = (float)((t0 > 0.f) - (t0 < 0.f));
    float s1 = (float)((t1 > 0.f) - (t1 < 0.f));
    t0 = s0 * powf(fabsf(t0) + 1e-6f, pp) * ws;
    t1 = s1 * powf(fabsf(t1) + 1e-6f, pp) * ws;

    float a0 = 0.f, a1 = 0.f, a2 = 0.f, a3 = 0.f;
    for (int j = tid; j < 512; j += 128) {
        float hsum = fmaf(t0, cpb_w1[j], fmaf(t1, cpb_w1[512 + j], cpb_b1[j]));
        hsum = fmaxf(hsum, 0.f);
        a0 = fmaf(hsum, cpb_w2[j * 4 + 0], a0);
        a1 = fmaf(hsum, cpb_w2[j * 4 + 1], a1);
        a2 = fmaf(hsum, cpb_w2[j * 4 + 2], a2);
        a3 = fmaf(hsum, cpb_w2[j * 4 + 3], a3);
    }
    red[tid][0] = a0; red[tid][1] = a1; red[tid][2] = a2; red[tid][3] = a3;
    __syncthreads();
    for (int s = 64; s > 0; s >>= 1) {
        if (tid < s) {
            red[tid][0] += red[tid + s][0];
            red[tid][1] += red[tid + s][1];
            red[tid][2] += red[tid + s][2];
            red[tid][3] += red[tid + s][3];
        }
        __syncthreads();
    }
    if (tid < 4) g_table[t * 4 + tid] = red[0][tid];
}

// ---------------------------------------------------------------------------
// Setup A2: bias -> bf16 C-fragment-packed layout
// ---------------------------------------------------------------------------
__global__ void bias_expand_kernel(const int* __restrict__ rel_index)
{
    int i = blockIdx.x * blockDim.x + threadIdx.x;
    if (i >= 4 * 4 * 8 * 32) return;
    int lane = i & 31, nt = (i >> 5) & 7, mtg = (i >> 8) & 3, h = i >> 10;
    int lr = lane >> 2, lc = lane & 3;
    int r0 = mtg * 16 + lr, r1 = r0 + 8;
    int c = nt * 8 + 2 * lc;
    float b00 = g_table[rel_index[r0 * 64 + c] * 4 + h];
    float b01 = g_table[rel_index[r0 * 64 + c + 1] * 4 + h];
    float b10 = g_table[rel_index[r1 * 64 + c] * 4 + h];
    float b11 = g_table[rel_index[r1 * 64 + c + 1] * 4 + h];
    __nv_bfloat162 lo = __floats2bfloat162_rn(b00, b01);
    __nv_bfloat162 hi = __floats2bfloat162_rn(b10, b11);
    uint2 v;
    v.x = *reinterpret_cast<unsigned*>(&lo);
    v.y = *reinterpret_cast<unsigned*>(&hi);
    g_biasf[i] = v;
}

// ---------------------------------------------------------------------------
// Setup B: tf32-round + B-pair-pack weights; q-columns pre-scaled by SCALE
// ---------------------------------------------------------------------------
__global__ void pack_kernel(const float* __restrict__ Wqkv,
                            const float* __restrict__ Wproj)
{
    int tid = blockIdx.x * blockDim.x + threadIdx.x;
    int stride = gridDim.x * blockDim.x;
    for (int i = tid; i < 128 * 384; i += stride) {
        int k = i / 384, n = i % 384;
        float w = Wqkv[(size_t)k * 384 + n];
        if (n < 128) w *= SCALE;          // fold q scale into weights
        g_wqkv_p4[bpack_idx(k, n, WQ4S)] = uaf(f2tf(w));
    }
    for (int i = tid; i < 128 * 128; i += stride) {
        int k = i / 128, n = i % 128;
        g_wproj_p4[bpack_idx(k, n, WP4S)] = uaf(f2tf(Wproj[(size_t)k * 128 + n]));
    }
}

// ---------------------------------------------------------------------------
// Main fused kernel: 1 window / CTA, 256 threads = 8 warps, 2 CTAs / SM
// ---------------------------------------------------------------------------
__global__ void __launch_bounds__(256, 2)
attn_kernel(const float* __restrict__ x,
            const float* __restrict__ bproj,
            float*       __restrict__ out)
{
    extern __shared__ float sm[];
    float* xq  = sm;              // row-major tf32: x, later O
    float* kTp = sm + OFF_KT;     // tf32 k, B-paired [channel][token]
    float* vsp = sm + OFF_VS;     // tf32 v, B-paired [token][channel]

    const int tid  = threadIdx.x;
    const int lane = tid & 31;
    const int wid  = tid >> 5;    // 0..7
    const int lr   = lane >> 2;
    const int lc   = lane & 3;
    const int b    = blockIdx.x;
    const int h    = wid >> 1;
    const int mh   = wid & 1;

    // ---- load x -> tf32, row-major ----
    const float4* xb = (const float4*)(x + (size_t)b * NTOK * DIM);
    #pragma unroll
    for (int i = 0; i < 8; i++) {
        int f = tid + i * 256;
        float4 v = xb[f];
        int r = f >> 5, c0 = (f & 31) << 2;
        float4 w = make_float4(uaf(f2tf(v.x)), uaf(f2tf(v.y)),
                               uaf(f2tf(v.z)), uaf(f2tf(v.w)));
        *(float4*)(xq + r * XQS + c0) = w;
    }
    __syncthreads();

    // ============ Phase 1 (merged): kv slab + q tile, shared A-fragments =====
    float qacc[2][4][4];
    {
        const float* wkv_base = g_wqkv_p4 + ((8 + wid * 2) * 8 + lr) * 4;
        const float* wq_base  = g_wqkv_p4 + ((h * 2) * 8 + lr) * 4;
        float kacc[4][4][4];
        #pragma unroll
        for (int mt = 0; mt < 4; mt++)
            #pragma unroll
            for (int nt = 0; nt < 4; nt++)
                #pragma unroll
                for (int e = 0; e < 4; e++) kacc[mt][nt][e] = 0.f;
        #pragma unroll
        for (int mt = 0; mt < 2; mt++)
            #pragma unroll
            for (int nt = 0; nt < 4; nt++)
                #pragma unroll
                for (int e = 0; e < 4; e++) qacc[mt][nt][e] = 0.f;

        #pragma unroll
        for (int kg = 0; kg < 16; kg++) {
            const float* wrk = wkv_base + (kg * 4 + lc) * WQ4S;
            const float* wrq = wq_base  + (kg * 4 + lc) * WQ4S;
            float4 bk0 = *(const float4*)(wrk);
            float4 bk1 = *(const float4*)(wrk + 32);
            float4 bq0 = *(const float4*)(wrq);
            float4 bq1 = *(const float4*)(wrq + 32);
            unsigned kb[4][2] = { { fau(bk0.x), fau(bk0.y) }, { fau(bk0.z), fau(bk0.w) },
                                  { fau(bk1.x), fau(bk1.y) }, { fau(bk1.z), fau(bk1.w) } };
            unsigned qb[4][2] = { { fau(bq0.x), fau(bq0.y) }, { fau(bq0.z), fau(bq0.w) },
                                  { fau(bq1.x), fau(bq1.y) }, { fau(bq1.z), fau(bq1.w) } };
            #pragma unroll
            for (int mt = 0; mt < 4; mt++) {
                const float* ap = xq + (mt * 16 + lr) * XQS + kg * 8 + lc;
                unsigned af[4] = { fau(ap[0]), fau(ap[8 * XQS]),
                                   fau(ap[4]), fau(ap[8 * XQS + 4]) };
                mma8(kacc[mt][0], af, kb[0]);
                mma8(kacc[mt][1], af, kb[1]);
                mma8(kacc[mt][2], af, kb[2]);
                mma8(kacc[mt][3], af, kb[3]);
                if ((mt >> 1) == mh) {           // warp-uniform branch
                    int qi = mt & 1;
                    mma8(qacc[qi][0], af, qb[0]);
                    mma8(qacc[qi][1], af, qb[1]);
                    mma8(qacc[qi][2], af, qb[2]);
                    mma8(qacc[qi][3], af, qb[3]);
                }
            }
        }

        // scatter k / v (tf32-rounded)
        if (wid < 4) {
            #pragma unroll
            for (int mt = 0; mt < 4; mt++)
                #pragma unroll
                for (int nt = 0; nt < 4; nt++)
                    #pragma unroll
                    for (int eh = 0; eh < 2; eh++)
                        #pragma unroll
                        for (int e = 0; e < 2; e++) {
                            int row = mt * 16 + lr + 8 * eh;
                            int ch = wid * 32 + nt * 8 + 2 * lc + e;
                            kTp[bpack_idx(ch, row, KTS)] =
                                uaf(f2tf(kacc[mt][nt][2 * eh + e]));
                        }
        } else {
            #pragma unroll
            for (int mt = 0; mt < 4; mt++)
                #pragma unroll
                for (int nt = 0; nt < 4; nt++)
                    #pragma unroll
                    for (int eh = 0; eh < 2; eh++)
                        #pragma unroll
                        for (int e = 0; e < 2; e++) {
                            int row = mt * 16 + lr + 8 * eh;
                            int ch = (wid - 4) * 32 + nt * 8 + 2 * lc + e;
                            vsp[bpack_idx(row, ch, VSS)] =
                                uaf(f2tf(kacc[mt][nt][2 * eh + e]));
                        }
        }

        // round q in registers (scale already folded into weights)
        #pragma unroll
        for (int mt = 0; mt < 2; mt++)
            #pragma unroll
            for (int nt = 0; nt < 4; nt++)
                #pragma unroll
                for (int e = 0; e < 4; e++)
                    qacc[mt][nt][e] = uaf(f2tf(qacc[mt][nt][e]));
    }
    __syncthreads();

    // ============ Phases 2-4 fused, BOTH 16-row stripes interleaved ==========
    const int s0 = lr * 4 + (lc >> 1), s1 = s0 + 2;
    const int odd = lc & 1;

    // q C-layout -> A-fragments for both stripes
    unsigned aq[2][4][4];
    #pragma unroll
    for (int mt = 0; mt < 2; mt++)
        #pragma unroll
        for (int kg = 0; kg < 4; kg++) c2a(qacc[mt][kg], s0, s1, odd, aq[mt][kg]);

    // S = Q K^T for both stripes; B fragments shared
    float sacc[2][8][4];
    #pragma unroll
    for (int mt = 0; mt < 2; mt++)
        #pragma unroll
        for (int nt = 0; nt < 8; nt++)
            #pragma unroll
            for (int e = 0; e < 4; e++) sacc[mt][nt][e] = 0.f;

    #pragma unroll
    for (int kg = 0; kg < 4; kg++) {
        const float* krow = kTp + ((h * 4 + kg) * 4 + lc) * KTS;
        #pragma unroll
        for (int np = 0; np < 4; np++) {
            float4 kv4 = *(const float4*)(krow + np * 32 + lr * 4);
            unsigned b0[2] = { fau(kv4.x), fau(kv4.y) };
            unsigned b1[2] = { fau(kv4.z), fau(kv4.w) };
            mma8(sacc[0][2 * np],     aq[0][kg], b0);
            mma8(sacc[0][2 * np + 1], aq[0][kg], b1);
            mma8(sacc[1][2 * np],     aq[1][kg], b0);
            mma8(sacc[1][2 * np + 1], aq[1][kg], b1);
        }
    }

    // bias for both stripes (batched loads)
    uint2 bfr[2][8];
    #pragma unroll
    for (int mt = 0; mt < 2; mt++) {
        const uint2* bp = g_biasf + ((h * 4 + (2 * mh + mt)) * 8) * 32 + lane;
        #pragma unroll
        for (int nt = 0; nt < 8; nt++) bfr[mt][nt] = bp[nt * 32];
    }

    // softmax WITHOUT max-subtraction (scores are tiny; exact math)
    float i0[2], i1[2];
    #pragma unroll
    for (int mt = 0; mt < 2; mt++) {
        float sum0 = 0.f, sum1 = 0.f;
        #pragma unroll
        for (int nt = 0; nt < 8; nt++) {
            __nv_bfloat162 lo = *reinterpret_cast<__nv_bfloat162*>(&bfr[mt][nt].x);
            __nv_bfloat162 hi = *reinterpret_cast<__nv_bfloat162*>(&bfr[mt][nt].y);
            float2 flo = __bfloat1622float2(lo);
            float2 fhi = __bfloat1622float2(hi);
            sacc[mt][nt][0] = __expf(sacc[mt][nt][0] + flo.x); sum0 += sacc[mt][nt][0];
            sacc[mt][nt][1] = __expf(sacc[mt][nt][1] + flo.y); sum0 += sacc[mt][nt][1];
            sacc[mt][nt][2] = __expf(sacc[mt][nt][2] + fhi.x); sum1 += sacc[mt][nt][2];
            sacc[mt][nt][3] = __expf(sacc[mt][nt][3] + fhi.y); sum1 += sacc[mt][nt][3];
        }
        sum0 += __shfl_xor_sync(0xffffffffu, sum0, 1);
        sum0 += __shfl_xor_sync(0xffffffffu, sum0, 2);
        sum1 += __shfl_xor_sync(0xffffffffu, sum1, 1);
        sum1 += __shfl_xor_sync(0xffffffffu, sum1, 2);
        i0[mt] = 1.0f / sum0;
        i1[mt] = 1.0f / sum1;
    }
    #pragma unroll
    for (int mt = 0; mt < 2; mt++)
        #pragma unroll
        for (int nt = 0; nt < 8; nt++) {
            sacc[mt][nt][0] = uaf(f2tf(sacc[mt][nt][0] * i0[mt]));
            sacc[mt][nt][1] = uaf(f2tf(sacc[mt][nt][1] * i0[mt]));
            sacc[mt][nt][2] = uaf(f2tf(sacc[mt][nt][2] * i1[mt]));
            sacc[mt][nt][3] = uaf(f2tf(sacc[mt][nt][3] * i1[mt]));
        }

    // O = P V for both stripes; V fragments shared
    float oacc[2][4][4];
    #pragma unroll
    for (int mt = 0; mt < 2; mt++)
        #pragma unroll
        for (int nt2 = 0; nt2 < 4; nt2++)
            #pragma unroll
            for (int e = 0; e < 4; e++) oacc[mt][nt2][e] = 0.f;

    #pragma unroll
    for (int kg = 0; kg < 8; kg++) {
        unsigned ap0[4], ap1[4];
        c2a(sacc[0][kg], s0, s1, odd, ap0);
        c2a(sacc[1][kg], s0, s1, odd, ap1);
        const float* vrow = vsp + (kg * 4 + lc) * VSS;
        #pragma unroll
        for (int np2 = 0; np2 < 2; np2++) {
            float4 vv = *(const float4*)(vrow + (2 * h + np2) * 32 + lr * 4);
            unsigned b0[2] = { fau(vv.x), fau(vv.y) };
            unsigned b1[2] = { fau(vv.z), fau(vv.w) };
            mma8(oacc[0][np2 * 2],     ap0, b0);
            mma8(oacc[0][np2 * 2 + 1], ap0, b1);
            mma8(oacc[1][np2 * 2],     ap1, b0);
            mma8(oacc[1][np2 * 2 + 1], ap1, b1);
        }
    }

    // O -> xq row-major (x dead)
    #pragma unroll
    for (int mt = 0; mt < 2; mt++)
        #pragma unroll
        for (int nt2 = 0; nt2 < 4; nt2++)
            #pragma unroll
            for (int eh = 0; eh < 2; eh++)
                #pragma unroll
                for (int e = 0; e < 2; e++) {
                    int row = mh * 32 + mt * 16 + lr + 8 * eh;
                    int ch = h * 32 + nt2 * 8 + 2 * lc + e;
                    xq[row * XQS + ch] = uaf(f2tf(oacc[mt][nt2][2 * eh + e]));
                }

    // phase-5 first weight fragments: issue loads BEFORE the barrier so their
    // L2 latency drains during barrier arrival/wait
    const int mh5 = wid & 1;
    const int sl  = wid >> 1;
    const float* wbase = g_wproj_p4 + ((sl * 2) * 8 + lr) * 4;
    float4 bv0 = *(const float4*)(wbase + lc * WP4S);
    float4 bv1 = *(const float4*)(wbase + lc * WP4S + 32);
    __syncthreads();

    // =================== Phase 5: Y = tf32(O) @ tf32(Wproj) + b ===============
    {
        float acc5[2][4][4];
        #pragma unroll
        for (int m = 0; m < 2; m++)
            #pragma unroll
            for (int j = 0; j < 4; j++)
                #pragma unroll
                for (int e = 0; e < 4; e++) acc5[m][j][e] = 0.f;

        #pragma unroll
        for (int kg = 0; kg < 16; kg++) {
            int nkg = (kg < 15) ? kg + 1 : 15;
            float4 nb0 = *(const float4*)(wbase + (nkg * 4 + lc) * WP4S);
            float4 nb1 = *(const float4*)(wbase + (nkg * 4 + lc) * WP4S + 32);
            unsigned b0[2] = { fau(bv0.x), fau(bv0.y) };
            unsigned b1[2] = { fau(bv0.z), fau(bv0.w) };
            unsigned b2[2] = { fau(bv1.x), fau(bv1.y) };
            unsigned b3[2] = { fau(bv1.z), fau(bv1.w) };
            #pragma unroll
            for (int m = 0; m < 2; m++) {
                const float* ap = xq + ((mh5 * 2 + m) * 16 + lr) * XQS + kg * 8 + lc;
                unsigned af[4] = { fau(ap[0]), fau(ap[8 * XQS]),
                                   fau(ap[4]), fau(ap[8 * XQS + 4]) };
                mma8(acc5[m][0], af, b0);
                mma8(acc5[m][1], af, b1);
                mma8(acc5[m][2], af, b2);
                mma8(acc5[m][3], af, b3);
            }
            bv0 = nb0; bv1 = nb1;
        }

        float* obp = out + (size_t)b * NTOK * DIM;
        #pragma unroll
        for (int m = 0; m < 2; m++)
            #pragma unroll
            for (int j = 0; j < 4; j++) {
                int c0 = sl * 32 + j * 8 + 2 * lc;
                float2 bb = *(const float2*)(bproj + c0);
                #pragma unroll
                for (int eh = 0; eh < 2; eh++) {
                    int row = (mh5 * 2 + m) * 16 + lr + 8 * eh;
                    *(float2*)(obp + row * DIM + c0) =
                        make_float2(acc5[m][j][2 * eh] + bb.x,
                                    acc5[m][j][2 * eh + 1] + bb.y);
                }
            }
    }
}

// ---------------------------------------------------------------------------
// Launch
// ---------------------------------------------------------------------------
extern "C" void kernel_launch(void* const* d_in, const int* in_sizes, int n_in,
                              void* d_out, int out_size)
{
    const float* x        = (const float*)d_in[0];
    const float* Wqkv     = (const float*)d_in[1];
    const float* Wproj    = (const float*)d_in[2];
    const float* bproj    = (const float*)d_in[3];
    const float* cpb_w1   = (const float*)d_in[4];
    const float* cpb_b1   = (const float*)d_in[5];
    const float* cpb_w2   = (const float*)d_in[6];
    const float* h_times  = (const float*)d_in[7];
    const float* pow_para = (const float*)d_in[8];
    const float* ws1      = (const float*)d_in[9];
    const float* ws2      = (const float*)d_in[10];
    const int*   rel_idx  = (const int*)d_in[11];
    const float* coords   = (const float*)d_in[12];

    int nwin = in_sizes[0] / (NTOK * DIM);

    int smem_bytes = SMEM_FLOATS * (int)sizeof(float);
    cudaFuncSetAttribute(attn_kernel,
                         cudaFuncAttributeMaxDynamicSharedMemorySize, smem_bytes);

    cpb_table_kernel<<<225, 128>>>(cpb_w1, cpb_b1, cpb_w2, h_times, pow_para,
                                   ws1, ws2, coords);
    bias_expand_kernel<<<16, 256>>>(rel_idx);
    pack_kernel<<<192, 256>>>(Wqkv, Wproj);
    attn_kernel<<<nwin, 256, smem_bytes>>>(x, bproj, (float*)d_out);
}